// round 16
// baseline (speedup 1.0000x reference)
#include <cuda_runtime.h>
#include <cuda_fp16.h>
#include <math.h>
#include <cstdint>

#define E_N     20000
#define KSEL    20
#define D_      128
#define F1_     512
#define F2_     128
#define NT_     2
#define NNODES  200000
#define NEDGES  500000
#define EPSV    1e-5f
#define PCH     12

// Scratch (allocation-free rule: __device__ globals)
static __device__ __half g_Pn[(size_t)NNODES * F1_];
static __device__ __half g_Pe[(size_t)NEDGES * F1_];
static __device__ __half g_g [(size_t)NT_ * E_N * F1_];
static __device__ __half g_H [(size_t)E_N * F1_];
static __device__ float  g_flag[NT_ * E_N];
static __device__ float  g_G[PCH * F1_];
#define PANEL_H 17408
#define PANEL_B (PANEL_H * 2)       // 34816 bytes
static __device__ __align__(16) __half g_img[5][4][PANEL_H];

#define NODE_BLKS ((NNODES + 127) / 128)   // 1563
#define EDGE_BLKS ((NEDGES + 127) / 128)   // 3907
#define PRE_GRID  152
#define NODE_CTAS 43                        // 43*36.3 ~ 109*35.8 (balanced)

__device__ __forceinline__ void mma_f16(float* c, const uint32_t* a, const uint32_t* b) {
    asm volatile("mma.sync.aligned.m16n8k16.row.col.f32.f16.f16.f32 "
                 "{%0,%1,%2,%3}, {%4,%5,%6,%7}, {%8,%9}, {%0,%1,%2,%3};"
                 : "+f"(c[0]), "+f"(c[1]), "+f"(c[2]), "+f"(c[3])
                 : "r"(a[0]), "r"(a[1]), "r"(a[2]), "r"(a[3]),
                   "r"(b[0]), "r"(b[1]));
}
__device__ __forceinline__ void ldsm_x4(uint32_t& r0, uint32_t& r1, uint32_t& r2,
                                        uint32_t& r3, uint32_t addr) {
    asm volatile("ldmatrix.sync.aligned.m8n8.x4.shared.b16 {%0,%1,%2,%3}, [%4];"
                 : "=r"(r0), "=r"(r1), "=r"(r2), "=r"(r3) : "r"(addr));
}
__device__ __forceinline__ uint32_t smem_u32(const void* p) {
    uint32_t a;
    asm("{ .reg .u64 t; cvta.to.shared.u64 t, %1; cvt.u32.u64 %0, t; }" : "=r"(a) : "l"(p));
    return a;
}
__device__ __forceinline__ unsigned long long pk2(float x, float y) {
    unsigned long long r;
    asm("mov.b64 %0, {%1, %2};" : "=l"(r) : "f"(x), "f"(y));
    return r;
}
__device__ __forceinline__ void cp_async16(uint32_t dst, const void* src) {
    asm volatile("cp.async.ca.shared.global [%0], [%1], 16;"
                 :: "r"(dst), "l"(__cvta_generic_to_global(src)) : "memory");
}
__device__ __forceinline__ void cp_commit() {
    asm volatile("cp.async.commit_group;" ::: "memory");
}
__device__ __forceinline__ void cp_wait0() {
    asm volatile("cp.async.wait_group 0;" ::: "memory");
}

// ---------------------------------------------------------------------------
// Weight prep (unchanged)
// ---------------------------------------------------------------------------
__global__ void k_prep(const float* __restrict__ fc1_w,
                       const float* __restrict__ fc1s_w,
                       const float* __restrict__ fc2s_w,
                       const float* __restrict__ fc2_w) {
    int idx = blockIdx.x * 256 + threadIdx.x;
    int k = idx & 127;
    int n = (idx >> 7) & 127;
    int p = (idx >> 14) & 3;
    int m = idx >> 16;
    float v;
    if      (m == 0) v = fc1_w [(size_t)k          * 512 + p * 128 + n];
    else if (m == 1) v = fc1_w [(size_t)(128 + k)  * 512 + p * 128 + n];
    else if (m == 2) v = fc1s_w[(size_t)k          * 512 + p * 128 + n];
    else if (m == 3) v = fc2s_w[(size_t)(p * 128 + k) * 128 + n];
    else             v = fc2_w [(size_t)(p * 128 + k) * 128 + n];
    g_img[m][p][n * 136 + k] = __float2half(v);
}

// ---------------------------------------------------------------------------
// Chebyshev prolog, degree 12 (unchanged)
// ---------------------------------------------------------------------------
__global__ void __launch_bounds__(512) k_cheb(const float* __restrict__ time_w,
                                              const float* __restrict__ time_b,
                                              const float* __restrict__ fc1_w) {
    __shared__ float teq[PCH][100];
    const int tid = threadIdx.x;
    for (int i = tid; i < PCH * 100; i += 512) {
        int q = i / 100, j = i - q * 100;
        float xq  = cospif((q + 0.5f) / (float)PCH);
        float dtq = 0.5f * (xq + 1.0f);
        teq[q][j] = cosf(dtq * time_w[j] + time_b[j]);
    }
    __syncthreads();
    const float* __restrict__ W1t = fc1_w + (size_t)256 * 512;
    float M[PCH];
#pragma unroll
    for (int q = 0; q < PCH; q++) M[q] = 0.f;
    for (int j = 0; j < 100; j++) {
        float w = W1t[(size_t)j * 512 + tid];
#pragma unroll
        for (int q = 0; q < PCH; q++) M[q] += teq[q][j] * w;
    }
#pragma unroll
    for (int p = 0; p < PCH; p++) {
        float s = 0.f;
#pragma unroll
        for (int q = 0; q < PCH; q++)
            s += cospif(p * (q + 0.5f) / (float)PCH) * M[q];
        g_G[p * 512 + tid] = s * ((p == 0 ? 1.0f : 2.0f) / (float)PCH);
    }
}

// ===========================================================================
// fp16 mma machinery (ldmatrix fragment loads)
// ===========================================================================
#define SMEM_64   (64 * 136 * 2 + 128 * 136 * 2)
#define SMEM_PRE  (4 * PANEL_B + 2 * PANEL_B)    // B[4] + A + St = 208896

// 8 warps as 2(M) x 4(N); warp tile 32x32; ldmatrix fragments (src1/gemm2).
#define FP16_MAINLOOP_LDSM(AsU, BsU, acc, wm, wn)                              \
    {                                                                          \
        const int lane_ = threadIdx.x & 31;                                    \
        uint32_t a_ad[2], b_ad[2];                                             \
        _Pragma("unroll")                                                      \
        for (int mt = 0; mt < 2; mt++)                                         \
            a_ad[mt] = (AsU) + ((wm) * 32 + mt * 16 + (lane_ & 15)) * 272      \
                       + ((lane_ >> 4) & 1) * 16;                              \
        _Pragma("unroll")                                                      \
        for (int j = 0; j < 2; j++)                                            \
            b_ad[j] = (BsU) + ((wn) * 32 + j * 16 + ((lane_ >> 4) << 3)        \
                       + (lane_ & 7)) * 272 + ((lane_ >> 3) & 1) * 16;         \
        _Pragma("unroll")                                                      \
        for (int ks = 0; ks < 8; ks++) {                                       \
            const int kb = ks * 32;                                            \
            uint32_t af[2][4], bf[4][2];                                       \
            _Pragma("unroll")                                                  \
            for (int mt = 0; mt < 2; mt++)                                     \
                ldsm_x4(af[mt][0], af[mt][1], af[mt][2], af[mt][3],            \
                        a_ad[mt] + kb);                                        \
            _Pragma("unroll")                                                  \
            for (int j = 0; j < 2; j++)                                        \
                ldsm_x4(bf[2 * j][0], bf[2 * j][1], bf[2 * j + 1][0],          \
                        bf[2 * j + 1][1], b_ad[j] + kb);                       \
            _Pragma("unroll")                                                  \
            for (int mt = 0; mt < 2; mt++)                                     \
                _Pragma("unroll")                                              \
                for (int nt = 0; nt < 4; nt++)                                 \
                    mma_f16(acc[mt][nt], af[mt], bf[nt]);                      \
        }                                                                      \
    }

// ---------------------------------------------------------------------------
// k_pre persistent: B panels (all 4) resident in smem for the CTA lifetime.
// 152 CTAs (1/SM), 512 threads, 16 warps as 4(M) x 4(N), warp tile 32x32.
// Each CTA loops over ~36 row tiles of its table (nodes or edges).
// ---------------------------------------------------------------------------
__global__ void __launch_bounds__(512, 1) k_pre_p(const float* __restrict__ An,
                                                  const float* __restrict__ Ae) {
    extern __shared__ char smem[];
    const int tid = threadIdx.x;
    int which, t0, stride, ntiles, N;
    const float* A;
    if (blockIdx.x < NODE_CTAS) {
        which = 0; A = An; N = NNODES;
        t0 = blockIdx.x; stride = NODE_CTAS; ntiles = NODE_BLKS;
    } else {
        which = 1; A = Ae; N = NEDGES;
        t0 = blockIdx.x - NODE_CTAS; stride = PRE_GRID - NODE_CTAS;
        ntiles = EDGE_BLKS;
    }
    __half* __restrict__ C = which ? g_Pe : g_Pn;
    const uint32_t base = smem_u32(smem);
    const uint32_t AsU = base + 4 * PANEL_B;
    __half (*As)[136] = (__half(*)[136])(smem + 4 * PANEL_B);
    __half (*St)[136] = (__half(*)[136])(smem + 5 * PANEL_B);

    // Load ALL 4 B panels once (CTA-resident for the whole kernel)
    {
        const __half* srcp = g_img[which][0];
        for (int i = tid; i < 4 * PANEL_H / 8; i += 512)
            cp_async16(base + i * 16, srcp + i * 8);
        cp_commit();
    }

    const int lane = tid & 31, wid = tid >> 5;
    const int wm = wid >> 2, wn = wid & 3;       // 4(M) x 4(N)
    const int g = lane >> 2, c = lane & 3;

    uint32_t a_ad[2], b_off[2];
#pragma unroll
    for (int mt = 0; mt < 2; mt++)
        a_ad[mt] = AsU + (wm * 32 + mt * 16 + (lane & 15)) * 272
                   + ((lane >> 4) & 1) * 16;
#pragma unroll
    for (int j = 0; j < 2; j++)
        b_off[j] = (wn * 32 + j * 16 + ((lane >> 4) << 3) + (lane & 7)) * 272
                   + ((lane >> 3) & 1) * 16;

    cp_wait0();
    __syncthreads();   // B resident

    for (int t = t0; t < ntiles; t += stride) {
        const int m0 = t * 128;
        // A tile 128x128 fp32 -> fp16
#pragma unroll
        for (int it = 0; it < 8; it++) {
            int idx = tid + it * 512;
            int r = idx >> 5, q = idx & 31;
            float4 v = make_float4(0.f, 0.f, 0.f, 0.f);
            if (m0 + r < N) v = *(const float4*)(A + (size_t)(m0 + r) * 128 + q * 4);
            __half2 h01 = __floats2half2_rn(v.x, v.y);
            __half2 h23 = __floats2half2_rn(v.z, v.w);
            *(uint2*)&As[r][q * 4] = make_uint2(*(uint32_t*)&h01, *(uint32_t*)&h23);
        }
        __syncthreads();

        for (int p = 0; p < 4; p++) {
            const uint32_t Bcur = base + p * PANEL_B;
            float acc[2][4][4] = {};
#pragma unroll
            for (int ks = 0; ks < 8; ks++) {
                const int kb = ks * 32;
                uint32_t af[2][4], bf[4][2];
#pragma unroll
                for (int mt = 0; mt < 2; mt++)
                    ldsm_x4(af[mt][0], af[mt][1], af[mt][2], af[mt][3],
                            a_ad[mt] + kb);
#pragma unroll
                for (int j = 0; j < 2; j++)
                    ldsm_x4(bf[2 * j][0], bf[2 * j][1], bf[2 * j + 1][0],
                            bf[2 * j + 1][1], Bcur + b_off[j] + kb);
#pragma unroll
                for (int mt = 0; mt < 2; mt++)
#pragma unroll
                    for (int nt = 0; nt < 4; nt++)
                        mma_f16(acc[mt][nt], af[mt], bf[nt]);
            }
            __syncthreads();   // previous stg done reading St

            // Stage fragments (conflict-free STS.32 pairs)
#pragma unroll
            for (int mt = 0; mt < 2; mt++) {
#pragma unroll
                for (int nt = 0; nt < 4; nt++) {
                    int rl = wm * 32 + mt * 16 + g;
                    int cl = wn * 32 + nt * 8 + c * 2;
                    *(__half2*)&St[rl][cl] =
                        __floats2half2_rn(acc[mt][nt][0], acc[mt][nt][1]);
                    *(__half2*)&St[rl + 8][cl] =
                        __floats2half2_rn(acc[mt][nt][2], acc[mt][nt][3]);
                }
            }
            __syncthreads();

            // Coalesced write-out: full 256B rows via STG.128
            const int n0 = p * 128;
#pragma unroll
            for (int it = 0; it < 4; it++) {
                int idx = tid + it * 512;
                int r = idx >> 4, q = idx & 15;
                if (m0 + r < N)
                    *(uint4*)(C + (size_t)(m0 + r) * 512 + n0 + q * 8) =
                        *(const uint4*)&St[r][q * 8];
            }
        }
        __syncthreads();   // all panels done before next tile overwrites A
    }
}

// ---------------------------------------------------------------------------
// Src GEMM1: g_H = relu(BN(memory[src] @ fc1s_w + b)). (unchanged)
// ---------------------------------------------------------------------------
__global__ void __launch_bounds__(256, 3) k_src1_h(
    const float* __restrict__ memory, const float* __restrict__ fc1s_b,
    const float* __restrict__ bn_g, const float* __restrict__ bn_b,
    const float* __restrict__ bn_m, const float* __restrict__ bn_v,
    const int* __restrict__ src) {
    extern __shared__ char smem[];
    __half (*As)[136] = (__half(*)[136])smem;
    __half (*Bs)[136] = (__half(*)[136])(smem + 64 * 136 * 2);
    __shared__ int nd[64];
    const int tid = threadIdx.x;
    const int m0 = blockIdx.x * 64;

    {
        const __half* srcp = g_img[2][blockIdx.y];
        uint32_t BsA = smem_u32(Bs);
        for (int i = tid; i < PANEL_H / 8; i += 256)
            cp_async16(BsA + i * 16, srcp + i * 8);
        cp_commit();
    }
    if (tid < 64) nd[tid] = (m0 + tid < E_N) ? src[m0 + tid] : 0;
    __syncthreads();
#pragma unroll
    for (int it = 0; it < 8; it++) {
        int idx = tid + it * 256;
        int r = idx >> 5, q = idx & 31;
        float4 v = make_float4(0.f, 0.f, 0.f, 0.f);
        if (m0 + r < E_N) v = *(const float4*)(memory + (size_t)nd[r] * 128 + q * 4);
        __half2 h01 = __floats2half2_rn(v.x, v.y);
        __half2 h23 = __floats2half2_rn(v.z, v.w);
        *(uint2*)&As[r][q * 4] = make_uint2(*(uint32_t*)&h01, *(uint32_t*)&h23);
    }
    cp_wait0();
    __syncthreads();

    const int lane = tid & 31, wid = tid >> 5;
    const int wm = wid >> 2, wn = wid & 3;
    const int g = lane >> 2, c = lane & 3;
    const uint32_t AsU = smem_u32(As), BsU = smem_u32(Bs);
    float acc[2][4][4] = {};
    FP16_MAINLOOP_LDSM(AsU, BsU, acc, wm, wn)

    const int n0 = blockIdx.y * 128;
#pragma unroll
    for (int nt = 0; nt < 4; nt++) {
        int col = n0 + wn * 32 + nt * 8 + c * 2;
        float s0 = bn_g[col]     * rsqrtf(bn_v[col]     + EPSV);
        float s1 = bn_g[col + 1] * rsqrtf(bn_v[col + 1] + EPSV);
        float o0 = fc1s_b[col]     - bn_m[col];
        float o1 = fc1s_b[col + 1] - bn_m[col + 1];
        float bb0 = bn_b[col], bb1 = bn_b[col + 1];
#pragma unroll
        for (int mt = 0; mt < 2; mt++) {
            int r = m0 + wm * 32 + mt * 16 + g;
            if (r < E_N)
                *(__half2*)(g_H + (size_t)r * 512 + col) = __floats2half2_rn(
                    fmaxf((acc[mt][nt][0] + o0) * s0 + bb0, 0.f),
                    fmaxf((acc[mt][nt][1] + o1) * s1 + bb1, 0.f));
            if (r + 8 < E_N)
                *(__half2*)(g_H + (size_t)(r + 8) * 512 + col) = __floats2half2_rn(
                    fmaxf((acc[mt][nt][2] + o0) * s0 + bb0, 0.f),
                    fmaxf((acc[mt][nt][3] + o1) * s1 + bb1, 0.f));
        }
    }
}

// ---------------------------------------------------------------------------
// Merged second GEMM (unchanged)
// ---------------------------------------------------------------------------
#define GEMM2_SRC_BLOCKS 313
__global__ void __launch_bounds__(256, 3) k_gemm2_h(
    const float* __restrict__ fc2s_b, const float* __restrict__ fc2_b,
    float* __restrict__ out) {
    extern __shared__ char smem[];
    __half (*As)[136] = (__half(*)[136])smem;
    __half (*Bs)[136] = (__half(*)[136])(smem + 64 * 136 * 2);
    const int tid = threadIdx.x;
    const int mode = (blockIdx.x >= GEMM2_SRC_BLOCKS) ? 1 : 0;
    const int blk  = mode ? (blockIdx.x - GEMM2_SRC_BLOCKS) : blockIdx.x;
    const int m0 = blk * 64;
    const int R  = mode ? NT_ * E_N : E_N;
    const __half* __restrict__ A = mode ? g_g : g_H;
    const float* __restrict__ bias = mode ? fc2_b : fc2s_b;
    const int wimg = mode ? 4 : 3;

    const int lane = tid & 31, wid = tid >> 5;
    const int wm = wid >> 2, wn = wid & 3;
    const int g = lane >> 2, c = lane & 3;
    const uint32_t AsU = smem_u32(As), BsU = smem_u32(Bs);
    float acc[2][4][4] = {};

    for (int kc = 0; kc < 4; kc++) {
        {
            const __half* srcp = g_img[wimg][kc];
            for (int i = tid; i < PANEL_H / 8; i += 256)
                cp_async16(BsU + i * 16, srcp + i * 8);
            cp_commit();
        }
#pragma unroll
        for (int it = 0; it < 8; it++) {
            int idx = tid + it * 256;
            int r = idx >> 5, q = idx & 31;
            uint2 v = make_uint2(0u, 0u);
            if (m0 + r < R)
                v = *(const uint2*)(A + (size_t)(m0 + r) * 512 + kc * 128 + q * 4);
            *(uint2*)&As[r][q * 4] = v;
        }
        cp_wait0();
        __syncthreads();
        FP16_MAINLOOP_LDSM(AsU, BsU, acc, wm, wn)
        __syncthreads();
    }

#pragma unroll
    for (int mt = 0; mt < 2; mt++) {
#pragma unroll
        for (int nt = 0; nt < 4; nt++) {
            int col = wn * 32 + nt * 8 + c * 2;
            float b0 = bias[col], b1 = bias[col + 1];
#pragma unroll
            for (int half = 0; half < 2; half++) {
                int r = m0 + wm * 32 + mt * 16 + g + half * 8;
                if (r >= R) continue;
                float v0 = acc[mt][nt][half * 2 + 0];
                float v1 = acc[mt][nt][half * 2 + 1];
                if (mode == 0) {
                    *(float2*)(out + (size_t)r * 384 + col) =
                        make_float2(v0 + b0, v1 + b1);
                } else {
                    int br = r / E_N, e = r - br * E_N;
                    float fl = g_flag[r];
                    *(float2*)(out + (size_t)e * 384 + 128 + br * 128 + col) =
                        make_float2(v0 + b0 * fl, v1 + b1 * fl);
                }
            }
        }
    }
}

// ---------------------------------------------------------------------------
// k_branch (unchanged from R15 champion)
// ---------------------------------------------------------------------------
__global__ void __launch_bounds__(128) k_branch(
    const float* __restrict__ sel_dt, const float* __restrict__ sel_w,
    const float* __restrict__ fc1_b,
    const float* __restrict__ ln1_g, const float* __restrict__ ln1_b,
    const int* __restrict__ sel_nodes, const int* __restrict__ sel_edges) {
    const int e = blockIdx.x, br = blockIdx.y;
    const int tid = threadIdx.x;
    __shared__ float ctd[KSEL][PCH * 2];
    __shared__ float wn[KSEL];
    __shared__ int   nd_s[KSEL], ed_s[KSEL];
    __shared__ float red_s[KSEL][4], red_q[KSEL][4];
    __shared__ float mu_s[KSEL], rs_s[KSEL];
    __shared__ float flag_s;

    const size_t base = ((size_t)br * E_N + e) * KSEL;
    if (tid < KSEL) {
        int k = tid;
        float dt = sel_dt[base + k];
        wn[k]   = sel_w[base + k];
        nd_s[k] = sel_nodes[base + k];
        ed_s[k] = sel_edges[base + k];
        float x = 2.f * dt - 1.f;
        float t0 = 1.f, t1 = x;
        ctd[k][0] = t0; ctd[k][1] = t0;
        ctd[k][2] = t1; ctd[k][3] = t1;
#pragma unroll
        for (int p = 2; p < PCH; p++) {
            float t2 = 2.f * x * t1 - t0;
            ctd[k][2 * p] = t2; ctd[k][2 * p + 1] = t2;
            t0 = t1; t1 = t2;
        }
    }
    __syncthreads();
    if (tid == 0) {
        float ws = 0.f;
#pragma unroll
        for (int k = 0; k < KSEL; k++) ws += wn[k];
        float fl = (ws > 0.f) ? 1.f : 0.f;
        flag_s = fl;
        float inv = fl > 0.f ? 1.f / ws : 0.f;
#pragma unroll
        for (int k = 0; k < KSEL; k++) wn[k] *= inv;
    }

    const int c0 = tid * 4;
    unsigned long long acc[KSEL][2];
    const float4 bv = *(const float4*)(fc1_b + c0);
#pragma unroll
    for (int k = 0; k < KSEL; k++) {
        uint2 vn = *(const uint2*)(g_Pn + (size_t)nd_s[k] * 512 + c0);
        uint2 ve = *(const uint2*)(g_Pe + (size_t)ed_s[k] * 512 + c0);
        float2 n0 = __half22float2(*(__half2*)&vn.x);
        float2 n1 = __half22float2(*(__half2*)&vn.y);
        float2 e0 = __half22float2(*(__half2*)&ve.x);
        float2 e1 = __half22float2(*(__half2*)&ve.y);
        acc[k][0] = pk2(n0.x + e0.x + bv.x, n0.y + e0.y + bv.y);
        acc[k][1] = pk2(n1.x + e1.x + bv.z, n1.y + e1.y + bv.w);
    }
    const uint32_t ctd_base = smem_u32(ctd);
#pragma unroll
    for (int half = 0; half < 2; half++) {
        unsigned long long Gd[6][2];
#pragma unroll
        for (int p = 0; p < 6; p++) {
            float4 gv = *(const float4*)(g_G + (half * 6 + p) * 512 + c0);
            Gd[p][0] = pk2(gv.x, gv.y);
            Gd[p][1] = pk2(gv.z, gv.w);
        }
#pragma unroll
        for (int k = 0; k < KSEL; k++) {
            uint32_t row = ctd_base + k * (PCH * 2 * 4) + half * 48;
#pragma unroll
            for (int p = 0; p < 6; p += 2) {
                unsigned long long t0, t1;
                asm("ld.shared.v2.b64 {%0, %1}, [%2];"
                    : "=l"(t0), "=l"(t1) : "r"(row + p * 8));
                asm("fma.rn.f32x2 %0, %1, %2, %0;" : "+l"(acc[k][0]) : "l"(t0), "l"(Gd[p][0]));
                asm("fma.rn.f32x2 %0, %1, %2, %0;" : "+l"(acc[k][1]) : "l"(t0), "l"(Gd[p][1]));
                asm("fma.rn.f32x2 %0, %1, %2, %0;" : "+l"(acc[k][0]) : "l"(t1), "l"(Gd[p + 1][0]));
                asm("fma.rn.f32x2 %0, %1, %2, %0;" : "+l"(acc[k][1]) : "l"(t1), "l"(Gd[p + 1][1]));
            }
        }
    }
    const int lane = tid & 31, warp = tid >> 5;
#pragma unroll
    for (int k = 0; k < KSEL; k++) {
        float2 a0 = *(float2*)&acc[k][0];
        float2 a1 = *(float2*)&acc[k][1];
        float s = a0.x + a0.y + a1.x + a1.y;
        float q = a0.x * a0.x + a0.y * a0.y + a1.x * a1.x + a1.y * a1.y;
#pragma unroll
        for (int o = 16; o > 0; o >>= 1) {
            s += __shfl_down_sync(0xffffffffu, s, o);
            q += __shfl_down_sync(0xffffffffu, q, o);
        }
        if (lane == 0) { red_s[k][warp] = s; red_q[k][warp] = q; }
    }
    __syncthreads();
    if (tid < KSEL) {
        float s = 0.f, q = 0.f;
#pragma unroll
        for (int w = 0; w < 4; w++) { s += red_s[tid][w]; q += red_q[tid][w]; }
        float mu = s * (1.f / 512.f);
        float var = q * (1.f / 512.f) - mu * mu;
        mu_s[tid] = mu;
        rs_s[tid] = rsqrtf(var + EPSV);
    }
    __syncthreads();
    const float4 lg = *(const float4*)(ln1_g + c0);
    const float4 lb = *(const float4*)(ln1_b + c0);
    const unsigned long long LG0 = pk2(lg.x, lg.y), LG1 = pk2(lg.z, lg.w);
    const unsigned long long LB0 = pk2(lb.x, lb.y), LB1 = pk2(lb.z, lb.w);
    float o0 = 0.f, o1 = 0.f, o2 = 0.f, o3 = 0.f;
#pragma unroll
    for (int k = 0; k < KSEL; k++) {
        float mu = mu_s[k], rs = rs_s[k], w = wn[k];
        unsigned long long rs2  = pk2(rs, rs);
        unsigned long long nmu2 = pk2(-mu, -mu);
        unsigned long long RL0, RL1, C0, C1, h0, h1;
        asm("mul.rn.f32x2 %0, %1, %2;" : "=l"(RL0) : "l"(rs2), "l"(LG0));
        asm("mul.rn.f32x2 %0, %1, %2;" : "=l"(RL1) : "l"(rs2), "l"(LG1));
        asm("fma.rn.f32x2 %0, %1, %2, %3;" : "=l"(C0) : "l"(nmu2), "l"(RL0), "l"(LB0));
        asm("fma.rn.f32x2 %0, %1, %2, %3;" : "=l"(C1) : "l"(nmu2), "l"(RL1), "l"(LB1));
        asm("fma.rn.f32x2 %0, %1, %2, %3;" : "=l"(h0) : "l"(acc[k][0]), "l"(RL0), "l"(C0));
        asm("fma.rn.f32x2 %0, %1, %2, %3;" : "=l"(h1) : "l"(acc[k][1]), "l"(RL1), "l"(C1));
        float2 f0 = *(float2*)&h0;
        float2 f1 = *(float2*)&h1;
        o0 += w * fmaxf(f0.x, 0.f);
        o1 += w * fmaxf(f0.y, 0.f);
        o2 += w * fmaxf(f1.x, 0.f);
        o3 += w * fmaxf(f1.y, 0.f);
    }
    __half2 h01 = __floats2half2_rn(o0, o1);
    __half2 h23 = __floats2half2_rn(o2, o3);
    *(uint2*)(g_g + ((size_t)br * E_N + e) * 512 + c0) =
        make_uint2(*(uint32_t*)&h01, *(uint32_t*)&h23);
    if (tid == 0) g_flag[br * E_N + e] = flag_s;
}

// ---------------------------------------------------------------------------
extern "C" void kernel_launch(void* const* d_in, const int* in_sizes, int n_in,
                              void* d_out, int out_size) {
    const float* memory    = (const float*)d_in[0];
    const float* edge_feat = (const float*)d_in[1];
    const float* sel_dt    = (const float*)d_in[2];
    const float* sel_w     = (const float*)d_in[3];
    const float* time_w    = (const float*)d_in[4];
    const float* time_b    = (const float*)d_in[5];
    const float* fc1_w     = (const float*)d_in[6];
    const float* fc1_b     = (const float*)d_in[7];
    const float* ln1_g     = (const float*)d_in[8];
    const float* ln1_b     = (const float*)d_in[9];
    const float* fc2_w     = (const float*)d_in[10];
    const float* fc2_b     = (const float*)d_in[11];
    const float* fc1s_w    = (const float*)d_in[12];
    const float* fc1s_b    = (const float*)d_in[13];
    const float* bn_g      = (const float*)d_in[14];
    const float* bn_b      = (const float*)d_in[15];
    const float* bn_m      = (const float*)d_in[16];
    const float* bn_v      = (const float*)d_in[17];
    const float* fc2s_w    = (const float*)d_in[18];
    const float* fc2s_b    = (const float*)d_in[19];
    const int* source_nodes = (const int*)d_in[20];
    const int* sel_nodes    = (const int*)d_in[21];
    const int* sel_edges    = (const int*)d_in[22];
    float* out = (float*)d_out;

    cudaFuncSetAttribute(k_pre_p,   cudaFuncAttributeMaxDynamicSharedMemorySize, SMEM_PRE);
    cudaFuncSetAttribute(k_src1_h,  cudaFuncAttributeMaxDynamicSharedMemorySize, SMEM_64);
    cudaFuncSetAttribute(k_gemm2_h, cudaFuncAttributeMaxDynamicSharedMemorySize, SMEM_64);

    k_prep<<<1280, 256>>>(fc1_w, fc1s_w, fc2s_w, fc2_w);
    k_cheb<<<1, 512>>>(time_w, time_b, fc1_w);
    // Persistent-B fp16 tensor-core precompute (1 CTA/SM, B resident)
    k_pre_p<<<PRE_GRID, 512, SMEM_PRE>>>(memory, edge_feat);
    k_src1_h<<<dim3((E_N + 63) / 64, 4), 256, SMEM_64>>>(
        memory, fc1s_b, bn_g, bn_b, bn_m, bn_v, source_nodes);
    // TPPR branches (R15 champion config)
    k_branch<<<dim3(E_N, NT_), 128>>>(sel_dt, sel_w, fc1_b, ln1_g, ln1_b,
                                      sel_nodes, sel_edges);
    k_gemm2_h<<<GEMM2_SRC_BLOCKS + (NT_ * E_N) / 64, 256, SMEM_64>>>(
        fc2s_b, fc2_b, out);
}

// round 17
// speedup vs baseline: 1.0826x; 1.0826x over previous
#include <cuda_runtime.h>
#include <cuda_fp16.h>
#include <math.h>
#include <cstdint>

#define E_N     20000
#define KSEL    20
#define D_      128
#define F1_     512
#define F2_     128
#define NT_     2
#define NNODES  200000
#define NEDGES  500000
#define EPSV    1e-5f
#define PCH     12

// Scratch (allocation-free rule: __device__ globals)
static __device__ __half g_Pn[(size_t)NNODES * F1_];
static __device__ __half g_Pe[(size_t)NEDGES * F1_];
static __device__ __half g_g [(size_t)NT_ * E_N * F1_];
static __device__ __half g_H [(size_t)E_N * F1_];
static __device__ float  g_flag[NT_ * E_N];
static __device__ float  g_G[PCH * F1_];
#define PANEL_H 17408
#define PANEL_B (PANEL_H * 2)       // 34816 bytes
static __device__ __align__(16) __half g_img[5][4][PANEL_H];

#define NODE_BLKS ((NNODES + 127) / 128)   // 1563
#define EDGE_BLKS ((NEDGES + 127) / 128)   // 3907
#define SRC_BLKS  ((E_N + 63) / 64)        // 313 (x4 panels)

__device__ __forceinline__ void mma_f16(float* c, const uint32_t* a, const uint32_t* b) {
    asm volatile("mma.sync.aligned.m16n8k16.row.col.f32.f16.f16.f32 "
                 "{%0,%1,%2,%3}, {%4,%5,%6,%7}, {%8,%9}, {%0,%1,%2,%3};"
                 : "+f"(c[0]), "+f"(c[1]), "+f"(c[2]), "+f"(c[3])
                 : "r"(a[0]), "r"(a[1]), "r"(a[2]), "r"(a[3]),
                   "r"(b[0]), "r"(b[1]));
}
__device__ __forceinline__ void ldsm_x4(uint32_t& r0, uint32_t& r1, uint32_t& r2,
                                        uint32_t& r3, uint32_t addr) {
    asm volatile("ldmatrix.sync.aligned.m8n8.x4.shared.b16 {%0,%1,%2,%3}, [%4];"
                 : "=r"(r0), "=r"(r1), "=r"(r2), "=r"(r3) : "r"(addr));
}
__device__ __forceinline__ uint32_t smem_u32(const void* p) {
    uint32_t a;
    asm("{ .reg .u64 t; cvta.to.shared.u64 t, %1; cvt.u32.u64 %0, t; }" : "=r"(a) : "l"(p));
    return a;
}
__device__ __forceinline__ unsigned long long pk2(float x, float y) {
    unsigned long long r;
    asm("mov.b64 %0, {%1, %2};" : "=l"(r) : "f"(x), "f"(y));
    return r;
}
__device__ __forceinline__ void cp_async16(uint32_t dst, const void* src) {
    asm volatile("cp.async.ca.shared.global [%0], [%1], 16;"
                 :: "r"(dst), "l"(__cvta_generic_to_global(src)) : "memory");
}
__device__ __forceinline__ void cp_commit() {
    asm volatile("cp.async.commit_group;" ::: "memory");
}
__device__ __forceinline__ void cp_wait0() {
    asm volatile("cp.async.wait_group 0;" ::: "memory");
}

// ---------------------------------------------------------------------------
// Weight prep (unchanged)
// ---------------------------------------------------------------------------
__global__ void k_prep(const float* __restrict__ fc1_w,
                       const float* __restrict__ fc1s_w,
                       const float* __restrict__ fc2s_w,
                       const float* __restrict__ fc2_w) {
    int idx = blockIdx.x * 256 + threadIdx.x;
    int k = idx & 127;
    int n = (idx >> 7) & 127;
    int p = (idx >> 14) & 3;
    int m = idx >> 16;
    float v;
    if      (m == 0) v = fc1_w [(size_t)k          * 512 + p * 128 + n];
    else if (m == 1) v = fc1_w [(size_t)(128 + k)  * 512 + p * 128 + n];
    else if (m == 2) v = fc1s_w[(size_t)k          * 512 + p * 128 + n];
    else if (m == 3) v = fc2s_w[(size_t)(p * 128 + k) * 128 + n];
    else             v = fc2_w [(size_t)(p * 128 + k) * 128 + n];
    g_img[m][p][n * 136 + k] = __float2half(v);
}

// ---------------------------------------------------------------------------
// Chebyshev prolog, degree 12 (unchanged)
// ---------------------------------------------------------------------------
__global__ void __launch_bounds__(512) k_cheb(const float* __restrict__ time_w,
                                              const float* __restrict__ time_b,
                                              const float* __restrict__ fc1_w) {
    __shared__ float teq[PCH][100];
    const int tid = threadIdx.x;
    for (int i = tid; i < PCH * 100; i += 512) {
        int q = i / 100, j = i - q * 100;
        float xq  = cospif((q + 0.5f) / (float)PCH);
        float dtq = 0.5f * (xq + 1.0f);
        teq[q][j] = cosf(dtq * time_w[j] + time_b[j]);
    }
    __syncthreads();
    const float* __restrict__ W1t = fc1_w + (size_t)256 * 512;
    float M[PCH];
#pragma unroll
    for (int q = 0; q < PCH; q++) M[q] = 0.f;
    for (int j = 0; j < 100; j++) {
        float w = W1t[(size_t)j * 512 + tid];
#pragma unroll
        for (int q = 0; q < PCH; q++) M[q] += teq[q][j] * w;
    }
#pragma unroll
    for (int p = 0; p < PCH; p++) {
        float s = 0.f;
#pragma unroll
        for (int q = 0; q < PCH; q++)
            s += cospif(p * (q + 0.5f) / (float)PCH) * M[q];
        g_G[p * 512 + tid] = s * ((p == 0 ? 1.0f : 2.0f) / (float)PCH);
    }
}

// ===========================================================================
// fp16 mma machinery (ldmatrix fragment loads)
// ===========================================================================
#define SMEM_64   (64 * 136 * 2 + 128 * 136 * 2)
#define SMEM_128  (3 * 128 * 136 * 2)            // As + B0 + B1 (stage aliases B)

// 8 warps as 2(M) x 4(N); warp tile 32x32; ldmatrix fragments (src/gemm2).
#define FP16_MAINLOOP_LDSM(AsU, BsU, acc, wm, wn)                              \
    {                                                                          \
        const int lane_ = threadIdx.x & 31;                                    \
        uint32_t a_ad[2], b_ad[2];                                             \
        _Pragma("unroll")                                                      \
        for (int mt = 0; mt < 2; mt++)                                         \
            a_ad[mt] = (AsU) + ((wm) * 32 + mt * 16 + (lane_ & 15)) * 272      \
                       + ((lane_ >> 4) & 1) * 16;                              \
        _Pragma("unroll")                                                      \
        for (int j = 0; j < 2; j++)                                            \
            b_ad[j] = (BsU) + ((wn) * 32 + j * 16 + ((lane_ >> 4) << 3)        \
                       + (lane_ & 7)) * 272 + ((lane_ >> 3) & 1) * 16;         \
        _Pragma("unroll")                                                      \
        for (int ks = 0; ks < 8; ks++) {                                       \
            const int kb = ks * 32;                                            \
            uint32_t af[2][4], bf[4][2];                                       \
            _Pragma("unroll")                                                  \
            for (int mt = 0; mt < 2; mt++)                                     \
                ldsm_x4(af[mt][0], af[mt][1], af[mt][2], af[mt][3],            \
                        a_ad[mt] + kb);                                        \
            _Pragma("unroll")                                                  \
            for (int j = 0; j < 2; j++)                                        \
                ldsm_x4(bf[2 * j][0], bf[2 * j][1], bf[2 * j + 1][0],          \
                        bf[2 * j + 1][1], b_ad[j] + kb);                       \
            _Pragma("unroll")                                                  \
            for (int mt = 0; mt < 2; mt++)                                     \
                _Pragma("unroll")                                              \
                for (int nt = 0; nt < 4; nt++)                                 \
                    mma_f16(acc[mt][nt], af[mt], bf[nt]);                      \
        }                                                                      \
    }

// ---------------------------------------------------------------------------
// Fused stage-1 kernel: three block regions.
//  [0, NODE_BLKS)                     : Pn tiles   (R15 k_pre body, which=0)
//  [NODE_BLKS, NODE_BLKS+EDGE_BLKS)   : Pe tiles   (R15 k_pre body, which=1)
//  [.., +4*SRC_BLKS)                  : src GEMM1  (R15 k_src1 body)
// 256 threads, <=104KB dyn smem, 2 CTAs/SM.
// ---------------------------------------------------------------------------
__global__ void __launch_bounds__(256, 2) k_fused1(
    const float* __restrict__ An, const float* __restrict__ Ae,
    const float* __restrict__ memory, const float* __restrict__ fc1s_b,
    const float* __restrict__ bn_g, const float* __restrict__ bn_b,
    const float* __restrict__ bn_m, const float* __restrict__ bn_v,
    const int* __restrict__ src) {
    extern __shared__ char smem[];
    const int tid = threadIdx.x;
    int blk = blockIdx.x;

    if (blk >= NODE_BLKS + EDGE_BLKS) {
        // ------------------- src GEMM1 region -------------------
        int sub = blk - (NODE_BLKS + EDGE_BLKS);
        int panel = sub / SRC_BLKS;
        int m0 = (sub - panel * SRC_BLKS) * 64;
        __half (*As)[136] = (__half(*)[136])smem;
        __half (*Bs)[136] = (__half(*)[136])(smem + 64 * 136 * 2);
        __shared__ int nd[64];
        {
            const __half* srcp = g_img[2][panel];
            uint32_t BsA = smem_u32(Bs);
            for (int i = tid; i < PANEL_H / 8; i += 256)
                cp_async16(BsA + i * 16, srcp + i * 8);
            cp_commit();
        }
        if (tid < 64) nd[tid] = (m0 + tid < E_N) ? src[m0 + tid] : 0;
        __syncthreads();
#pragma unroll
        for (int it = 0; it < 8; it++) {
            int idx = tid + it * 256;
            int r = idx >> 5, q = idx & 31;
            float4 v = make_float4(0.f, 0.f, 0.f, 0.f);
            if (m0 + r < E_N) v = *(const float4*)(memory + (size_t)nd[r] * 128 + q * 4);
            __half2 h01 = __floats2half2_rn(v.x, v.y);
            __half2 h23 = __floats2half2_rn(v.z, v.w);
            *(uint2*)&As[r][q * 4] = make_uint2(*(uint32_t*)&h01, *(uint32_t*)&h23);
        }
        cp_wait0();
        __syncthreads();

        const int lane = tid & 31, wid = tid >> 5;
        const int wm = wid >> 2, wn = wid & 3;
        const int g = lane >> 2, c = lane & 3;
        const uint32_t AsU = smem_u32(As), BsU = smem_u32(Bs);
        float acc[2][4][4] = {};
        FP16_MAINLOOP_LDSM(AsU, BsU, acc, wm, wn)

        const int n0 = panel * 128;
#pragma unroll
        for (int nt = 0; nt < 4; nt++) {
            int col = n0 + wn * 32 + nt * 8 + c * 2;
            float s0 = bn_g[col]     * rsqrtf(bn_v[col]     + EPSV);
            float s1 = bn_g[col + 1] * rsqrtf(bn_v[col + 1] + EPSV);
            float o0 = fc1s_b[col]     - bn_m[col];
            float o1 = fc1s_b[col + 1] - bn_m[col + 1];
            float bb0 = bn_b[col], bb1 = bn_b[col + 1];
#pragma unroll
            for (int mt = 0; mt < 2; mt++) {
                int r = m0 + wm * 32 + mt * 16 + g;
                if (r < E_N)
                    *(__half2*)(g_H + (size_t)r * 512 + col) = __floats2half2_rn(
                        fmaxf((acc[mt][nt][0] + o0) * s0 + bb0, 0.f),
                        fmaxf((acc[mt][nt][1] + o1) * s1 + bb1, 0.f));
                if (r + 8 < E_N)
                    *(__half2*)(g_H + (size_t)(r + 8) * 512 + col) = __floats2half2_rn(
                        fmaxf((acc[mt][nt][2] + o0) * s0 + bb0, 0.f),
                        fmaxf((acc[mt][nt][3] + o1) * s1 + bb1, 0.f));
            }
        }
        return;
    }

    // ------------------- P precompute region (R15 body) -------------------
    int which, N;
    const float* A;
    if (blk < NODE_BLKS) { which = 0; A = An; N = NNODES; }
    else                 { which = 1; A = Ae; N = NEDGES; blk -= NODE_BLKS; }
    __half* __restrict__ C = which ? g_Pe : g_Pn;
    const int m0 = blk * 128;
    __half (*As)[136] = (__half(*)[136])smem;
    const uint32_t AsU = smem_u32(smem);
    const uint32_t Bbase[2] = {AsU + PANEL_B, AsU + 2 * PANEL_B};

    // Prefetch panel 0 into B0
    {
        const __half* srcp = g_img[which][0];
        for (int i = tid; i < PANEL_H / 8; i += 256)
            cp_async16(Bbase[0] + i * 16, srcp + i * 8);
        cp_commit();
    }
    // A tile 128x128 fp32 -> fp16 (loaded once, reused across all 4 panels)
#pragma unroll
    for (int it = 0; it < 16; it++) {
        int idx = tid + it * 256;
        int r = idx >> 5, q = idx & 31;
        float4 v = make_float4(0.f, 0.f, 0.f, 0.f);
        if (m0 + r < N) v = *(const float4*)(A + (size_t)(m0 + r) * 128 + q * 4);
        __half2 h01 = __floats2half2_rn(v.x, v.y);
        __half2 h23 = __floats2half2_rn(v.z, v.w);
        *(uint2*)&As[r][q * 4] = make_uint2(*(uint32_t*)&h01, *(uint32_t*)&h23);
    }

    const int lane = tid & 31, wid = tid >> 5;
    const int wm = wid >> 1, wn = wid & 1;       // 4(M) x 2(N)
    const int g = lane >> 2, c = lane & 3;

    uint32_t a_ad[2], b_off[4];
#pragma unroll
    for (int mt = 0; mt < 2; mt++)
        a_ad[mt] = AsU + (wm * 32 + mt * 16 + (lane & 15)) * 272
                   + ((lane >> 4) & 1) * 16;
#pragma unroll
    for (int j = 0; j < 4; j++)
        b_off[j] = (wn * 64 + j * 16 + ((lane >> 4) << 3) + (lane & 7)) * 272
                   + ((lane >> 3) & 1) * 16;

    for (int p = 0; p < 4; p++) {
        const uint32_t Bcur = Bbase[p & 1];
        cp_wait0();
        __syncthreads();                          // panel p ready; A loads done

        float acc[2][8][4] = {};
#pragma unroll
        for (int ks = 0; ks < 8; ks++) {
            const int kb = ks * 32;
            uint32_t af[2][4], bf[8][2];
#pragma unroll
            for (int mt = 0; mt < 2; mt++)
                ldsm_x4(af[mt][0], af[mt][1], af[mt][2], af[mt][3], a_ad[mt] + kb);
#pragma unroll
            for (int j = 0; j < 4; j++)
                ldsm_x4(bf[2 * j][0], bf[2 * j][1], bf[2 * j + 1][0],
                        bf[2 * j + 1][1], Bcur + b_off[j] + kb);
#pragma unroll
            for (int mt = 0; mt < 2; mt++)
#pragma unroll
                for (int nt = 0; nt < 8; nt++)
                    mma_f16(acc[mt][nt], af[mt], bf[nt]);
        }
        __syncthreads();                          // all warps done reading Bcur

        // Prefetch next panel into the OTHER buffer (overlaps stage + STG)
        if (p < 3) {
            const __half* srcp = g_img[which][p + 1];
            const uint32_t Bnext = Bbase[(p + 1) & 1];
            for (int i = tid; i < PANEL_H / 8; i += 256)
                cp_async16(Bnext + i * 16, srcp + i * 8);
            cp_commit();
        }

        // Stage fragments into the just-consumed panel buffer (alias)
        __half (*St)[136] = (__half(*)[136])(smem + (size_t)(Bcur - AsU));
#pragma unroll
        for (int mt = 0; mt < 2; mt++) {
#pragma unroll
            for (int nt = 0; nt < 8; nt++) {
                int rl = wm * 32 + mt * 16 + g;
                int cl = wn * 64 + nt * 8 + c * 2;
                *(__half2*)&St[rl][cl] =
                    __floats2half2_rn(acc[mt][nt][0], acc[mt][nt][1]);
                *(__half2*)&St[rl + 8][cl] =
                    __floats2half2_rn(acc[mt][nt][2], acc[mt][nt][3]);
            }
        }
        __syncthreads();

        // Coalesced write-out: full 256B rows via STG.128
        const int n0 = p * 128;
#pragma unroll
        for (int it = 0; it < 8; it++) {
            int idx = tid + it * 256;
            int r = idx >> 4, q = idx & 15;
            if (m0 + r < N)
                *(uint4*)(C + (size_t)(m0 + r) * 512 + n0 + q * 8) =
                    *(const uint4*)&St[r][q * 8];
        }
    }
}

// ---------------------------------------------------------------------------
// Merged second GEMM (unchanged from R15)
// ---------------------------------------------------------------------------
#define GEMM2_SRC_BLOCKS 313
__global__ void __launch_bounds__(256, 3) k_gemm2_h(
    const float* __restrict__ fc2s_b, const float* __restrict__ fc2_b,
    float* __restrict__ out) {
    extern __shared__ char smem[];
    __half (*As)[136] = (__half(*)[136])smem;
    __half (*Bs)[136] = (__half(*)[136])(smem + 64 * 136 * 2);
    const int tid = threadIdx.x;
    const int mode = (blockIdx.x >= GEMM2_SRC_BLOCKS) ? 1 : 0;
    const int blk  = mode ? (blockIdx.x - GEMM2_SRC_BLOCKS) : blockIdx.x;
    const int m0 = blk * 64;
    const int R  = mode ? NT_ * E_N : E_N;
    const __half* __restrict__ A = mode ? g_g : g_H;
    const float* __restrict__ bias = mode ? fc2_b : fc2s_b;
    const int wimg = mode ? 4 : 3;

    const int lane = tid & 31, wid = tid >> 5;
    const int wm = wid >> 2, wn = wid & 3;
    const int g = lane >> 2, c = lane & 3;
    const uint32_t AsU = smem_u32(As), BsU = smem_u32(Bs);
    float acc[2][4][4] = {};

    for (int kc = 0; kc < 4; kc++) {
        {
            const __half* srcp = g_img[wimg][kc];
            for (int i = tid; i < PANEL_H / 8; i += 256)
                cp_async16(BsU + i * 16, srcp + i * 8);
            cp_commit();
        }
#pragma unroll
        for (int it = 0; it < 8; it++) {
            int idx = tid + it * 256;
            int r = idx >> 5, q = idx & 31;
            uint2 v = make_uint2(0u, 0u);
            if (m0 + r < R)
                v = *(const uint2*)(A + (size_t)(m0 + r) * 512 + kc * 128 + q * 4);
            *(uint2*)&As[r][q * 4] = v;
        }
        cp_wait0();
        __syncthreads();
        FP16_MAINLOOP_LDSM(AsU, BsU, acc, wm, wn)
        __syncthreads();
    }

#pragma unroll
    for (int mt = 0; mt < 2; mt++) {
#pragma unroll
        for (int nt = 0; nt < 4; nt++) {
            int col = wn * 32 + nt * 8 + c * 2;
            float b0 = bias[col], b1 = bias[col + 1];
#pragma unroll
            for (int half = 0; half < 2; half++) {
                int r = m0 + wm * 32 + mt * 16 + g + half * 8;
                if (r >= R) continue;
                float v0 = acc[mt][nt][half * 2 + 0];
                float v1 = acc[mt][nt][half * 2 + 1];
                if (mode == 0) {
                    *(float2*)(out + (size_t)r * 384 + col) =
                        make_float2(v0 + b0, v1 + b1);
                } else {
                    int br = r / E_N, e = r - br * E_N;
                    float fl = g_flag[r];
                    *(float2*)(out + (size_t)e * 384 + 128 + br * 128 + col) =
                        make_float2(v0 + b0 * fl, v1 + b1 * fl);
                }
            }
        }
    }
}

// ---------------------------------------------------------------------------
// k_branch (unchanged from R15 champion)
// ---------------------------------------------------------------------------
__global__ void __launch_bounds__(128) k_branch(
    const float* __restrict__ sel_dt, const float* __restrict__ sel_w,
    const float* __restrict__ fc1_b,
    const float* __restrict__ ln1_g, const float* __restrict__ ln1_b,
    const int* __restrict__ sel_nodes, const int* __restrict__ sel_edges) {
    const int e = blockIdx.x, br = blockIdx.y;
    const int tid = threadIdx.x;
    __shared__ float ctd[KSEL][PCH * 2];
    __shared__ float wn[KSEL];
    __shared__ int   nd_s[KSEL], ed_s[KSEL];
    __shared__ float red_s[KSEL][4], red_q[KSEL][4];
    __shared__ float mu_s[KSEL], rs_s[KSEL];
    __shared__ float flag_s;

    const size_t base = ((size_t)br * E_N + e) * KSEL;
    if (tid < KSEL) {
        int k = tid;
        float dt = sel_dt[base + k];
        wn[k]   = sel_w[base + k];
        nd_s[k] = sel_nodes[base + k];
        ed_s[k] = sel_edges[base + k];
        float x = 2.f * dt - 1.f;
        float t0 = 1.f, t1 = x;
        ctd[k][0] = t0; ctd[k][1] = t0;
        ctd[k][2] = t1; ctd[k][3] = t1;
#pragma unroll
        for (int p = 2; p < PCH; p++) {
            float t2 = 2.f * x * t1 - t0;
            ctd[k][2 * p] = t2; ctd[k][2 * p + 1] = t2;
            t0 = t1; t1 = t2;
        }
    }
    __syncthreads();
    if (tid == 0) {
        float ws = 0.f;
#pragma unroll
        for (int k = 0; k < KSEL; k++) ws += wn[k];
        float fl = (ws > 0.f) ? 1.f : 0.f;
        flag_s = fl;
        float inv = fl > 0.f ? 1.f / ws : 0.f;
#pragma unroll
        for (int k = 0; k < KSEL; k++) wn[k] *= inv;
    }

    const int c0 = tid * 4;
    unsigned long long acc[KSEL][2];
    const float4 bv = *(const float4*)(fc1_b + c0);
#pragma unroll
    for (int k = 0; k < KSEL; k++) {
        uint2 vn = *(const uint2*)(g_Pn + (size_t)nd_s[k] * 512 + c0);
        uint2 ve = *(const uint2*)(g_Pe + (size_t)ed_s[k] * 512 + c0);
        float2 n0 = __half22float2(*(__half2*)&vn.x);
        float2 n1 = __half22float2(*(__half2*)&vn.y);
        float2 e0 = __half22float2(*(__half2*)&ve.x);
        float2 e1 = __half22float2(*(__half2*)&ve.y);
        acc[k][0] = pk2(n0.x + e0.x + bv.x, n0.y + e0.y + bv.y);
        acc[k][1] = pk2(n1.x + e1.x + bv.z, n1.y + e1.y + bv.w);
    }
    const uint32_t ctd_base = smem_u32(ctd);
#pragma unroll
    for (int half = 0; half < 2; half++) {
        unsigned long long Gd[6][2];
#pragma unroll
        for (int p = 0; p < 6; p++) {
            float4 gv = *(const float4*)(g_G + (half * 6 + p) * 512 + c0);
            Gd[p][0] = pk2(gv.x, gv.y);
            Gd[p][1] = pk2(gv.z, gv.w);
        }
#pragma unroll
        for (int k = 0; k < KSEL; k++) {
            uint32_t row = ctd_base + k * (PCH * 2 * 4) + half * 48;
#pragma unroll
            for (int p = 0; p < 6; p += 2) {
                unsigned long long t0, t1;
                asm("ld.shared.v2.b64 {%0, %1}, [%2];"
                    : "=l"(t0), "=l"(t1) : "r"(row + p * 8));
                asm("fma.rn.f32x2 %0, %1, %2, %0;" : "+l"(acc[k][0]) : "l"(t0), "l"(Gd[p][0]));
                asm("fma.rn.f32x2 %0, %1, %2, %0;" : "+l"(acc[k][1]) : "l"(t0), "l"(Gd[p][1]));
                asm("fma.rn.f32x2 %0, %1, %2, %0;" : "+l"(acc[k][0]) : "l"(t1), "l"(Gd[p + 1][0]));
                asm("fma.rn.f32x2 %0, %1, %2, %0;" : "+l"(acc[k][1]) : "l"(t1), "l"(Gd[p + 1][1]));
            }
        }
    }
    const int lane = tid & 31, warp = tid >> 5;
#pragma unroll
    for (int k = 0; k < KSEL; k++) {
        float2 a0 = *(float2*)&acc[k][0];
        float2 a1 = *(float2*)&acc[k][1];
        float s = a0.x + a0.y + a1.x + a1.y;
        float q = a0.x * a0.x + a0.y * a0.y + a1.x * a1.x + a1.y * a1.y;
#pragma unroll
        for (int o = 16; o > 0; o >>= 1) {
            s += __shfl_down_sync(0xffffffffu, s, o);
            q += __shfl_down_sync(0xffffffffu, q, o);
        }
        if (lane == 0) { red_s[k][warp] = s; red_q[k][warp] = q; }
    }
    __syncthreads();
    if (tid < KSEL) {
        float s = 0.f, q = 0.f;
#pragma unroll
        for (int w = 0; w < 4; w++) { s += red_s[tid][w]; q += red_q[tid][w]; }
        float mu = s * (1.f / 512.f);
        float var = q * (1.f / 512.f) - mu * mu;
        mu_s[tid] = mu;
        rs_s[tid] = rsqrtf(var + EPSV);
    }
    __syncthreads();
    const float4 lg = *(const float4*)(ln1_g + c0);
    const float4 lb = *(const float4*)(ln1_b + c0);
    const unsigned long long LG0 = pk2(lg.x, lg.y), LG1 = pk2(lg.z, lg.w);
    const unsigned long long LB0 = pk2(lb.x, lb.y), LB1 = pk2(lb.z, lb.w);
    float o0 = 0.f, o1 = 0.f, o2 = 0.f, o3 = 0.f;
#pragma unroll
    for (int k = 0; k < KSEL; k++) {
        float mu = mu_s[k], rs = rs_s[k], w = wn[k];
        unsigned long long rs2  = pk2(rs, rs);
        unsigned long long nmu2 = pk2(-mu, -mu);
        unsigned long long RL0, RL1, C0, C1, h0, h1;
        asm("mul.rn.f32x2 %0, %1, %2;" : "=l"(RL0) : "l"(rs2), "l"(LG0));
        asm("mul.rn.f32x2 %0, %1, %2;" : "=l"(RL1) : "l"(rs2), "l"(LG1));
        asm("fma.rn.f32x2 %0, %1, %2, %3;" : "=l"(C0) : "l"(nmu2), "l"(RL0), "l"(LB0));
        asm("fma.rn.f32x2 %0, %1, %2, %3;" : "=l"(C1) : "l"(nmu2), "l"(RL1), "l"(LB1));
        asm("fma.rn.f32x2 %0, %1, %2, %3;" : "=l"(h0) : "l"(acc[k][0]), "l"(RL0), "l"(C0));
        asm("fma.rn.f32x2 %0, %1, %2, %3;" : "=l"(h1) : "l"(acc[k][1]), "l"(RL1), "l"(C1));
        float2 f0 = *(float2*)&h0;
        float2 f1 = *(float2*)&h1;
        o0 += w * fmaxf(f0.x, 0.f);
        o1 += w * fmaxf(f0.y, 0.f);
        o2 += w * fmaxf(f1.x, 0.f);
        o3 += w * fmaxf(f1.y, 0.f);
    }
    __half2 h01 = __floats2half2_rn(o0, o1);
    __half2 h23 = __floats2half2_rn(o2, o3);
    *(uint2*)(g_g + ((size_t)br * E_N + e) * 512 + c0) =
        make_uint2(*(uint32_t*)&h01, *(uint32_t*)&h23);
    if (tid == 0) g_flag[br * E_N + e] = flag_s;
}

// ---------------------------------------------------------------------------
extern "C" void kernel_launch(void* const* d_in, const int* in_sizes, int n_in,
                              void* d_out, int out_size) {
    const float* memory    = (const float*)d_in[0];
    const float* edge_feat = (const float*)d_in[1];
    const float* sel_dt    = (const float*)d_in[2];
    const float* sel_w     = (const float*)d_in[3];
    const float* time_w    = (const float*)d_in[4];
    const float* time_b    = (const float*)d_in[5];
    const float* fc1_w     = (const float*)d_in[6];
    const float* fc1_b     = (const float*)d_in[7];
    const float* ln1_g     = (const float*)d_in[8];
    const float* ln1_b     = (const float*)d_in[9];
    const float* fc2_w     = (const float*)d_in[10];
    const float* fc2_b     = (const float*)d_in[11];
    const float* fc1s_w    = (const float*)d_in[12];
    const float* fc1s_b    = (const float*)d_in[13];
    const float* bn_g      = (const float*)d_in[14];
    const float* bn_b      = (const float*)d_in[15];
    const float* bn_m      = (const float*)d_in[16];
    const float* bn_v      = (const float*)d_in[17];
    const float* fc2s_w    = (const float*)d_in[18];
    const float* fc2s_b    = (const float*)d_in[19];
    const int* source_nodes = (const int*)d_in[20];
    const int* sel_nodes    = (const int*)d_in[21];
    const int* sel_edges    = (const int*)d_in[22];
    float* out = (float*)d_out;

    cudaFuncSetAttribute(k_fused1,  cudaFuncAttributeMaxDynamicSharedMemorySize, SMEM_128);
    cudaFuncSetAttribute(k_gemm2_h, cudaFuncAttributeMaxDynamicSharedMemorySize, SMEM_64);

    k_prep<<<1280, 256>>>(fc1_w, fc1s_w, fc2s_w, fc2_w);
    k_cheb<<<1, 512>>>(time_w, time_b, fc1_w);
    // Fused stage 1: node P + edge P + src GEMM1 in one grid
    k_fused1<<<NODE_BLKS + EDGE_BLKS + 4 * SRC_BLKS, 256, SMEM_128>>>(
        memory, edge_feat, memory, fc1s_b, bn_g, bn_b, bn_m, bn_v, source_nodes);
    // TPPR branches (R15 champion config)
    k_branch<<<dim3(E_N, NT_), 128>>>(sel_dt, sel_w, fc1_b, ln1_g, ln1_b,
                                      sel_nodes, sel_edges);
    k_gemm2_h<<<GEMM2_SRC_BLOCKS + (NT_ * E_N) / 64, 256, SMEM_64>>>(
        fc2s_b, fc2_b, out);
}